// round 12
// baseline (speedup 1.0000x reference)
#include <cuda_runtime.h>
#include <cstdint>

#define CTX  2048
#define EMB  1024
#define NH   16
#define HD   64
#define BT   8192   // B*T

// Scratch (allocation-free rule: __device__ globals)
__device__ float g_q[BT * EMB];
__device__ float g_k[BT * EMB];
__device__ float g_v[BT * EMB];
__device__ float g_a[BT * EMB];

// ======================= helpers ===========================================
__device__ __forceinline__ uint32_t f2tf(float f) {
    uint32_t u;
    asm("cvt.rna.tf32.f32 %0, %1;" : "=r"(u) : "f"(f));
    return u;
}
// D(16x8,f32) += A(16x8,tf32,row) * B(8x8,tf32,col)
__device__ __forceinline__ void mma_tf32(float* d, const uint32_t* a,
                                         const uint32_t* b) {
    asm volatile(
        "mma.sync.aligned.m16n8k8.row.col.f32.tf32.tf32.f32 "
        "{%0,%1,%2,%3}, {%4,%5,%6,%7}, {%8,%9}, {%0,%1,%2,%3};"
        : "+f"(d[0]), "+f"(d[1]), "+f"(d[2]), "+f"(d[3])
        : "r"(a[0]), "r"(a[1]), "r"(a[2]), "r"(a[3]), "r"(b[0]), "r"(b[1]));
}
__device__ __forceinline__ uint32_t smem_u32(const void* p) {
    uint32_t a;
    asm("{ .reg .u64 t; cvta.to.shared.u64 t, %1; cvt.u32.u64 %0, t; }"
        : "=r"(a) : "l"(p));
    return a;
}
__device__ __forceinline__ void cp_async16(uint32_t dst, const void* src) {
    asm volatile("cp.async.cg.shared.global [%0], [%1], 16;"
                 :: "r"(dst), "l"(src));
}
#define CP_COMMIT() asm volatile("cp.async.commit_group;" ::: "memory")
#define CP_WAIT1()  asm volatile("cp.async.wait_group 1;" ::: "memory")

// ---------------------------------------------------------------------------
// GEMM core: C[m,n] = sum_k A[m,k] * W[n,k] + bias[n]
// CTA tile 128x128, 128 thr / 4 warps, warp tile 64x64 (R6 shape).
// K-chunks of 16 (ASTRIDE 20) -> smem 40.9KB -> 2 CTAs/SM for overlap.
// cvt.rna at fragment build (correctness-critical; truncation bias over
// K=1024 reached 1.5e-3 in R10).
// MODE 0: row-major out.  MODE 1: scatter to (B,H,T,D).
// ---------------------------------------------------------------------------
#define ASTRIDE 20
#define GTILE (128 * ASTRIDE)              // 2560 floats per operand stage
#define GEMM_SMEM (4 * GTILE * 4)          // A[2]+B[2] = 40960 bytes

template <int MODE>
__device__ __forceinline__
void gemm_core(const float* __restrict__ A, const float* __restrict__ W,
               const float* __restrict__ bias, float* __restrict__ C,
               float* sm, int m0, int n0) {
    const uint32_t sA = smem_u32(sm);
    const uint32_t sB = sA + 2 * GTILE * 4;

    const int tid  = threadIdx.x;
    const int wid  = tid >> 5;
    const int lane = tid & 31;
    const int g    = lane >> 2;
    const int t    = lane & 3;
    const int wm0  = (wid >> 1) * 64;
    const int wn0  = (wid & 1) * 64;

    float acc[4][8][4];
#pragma unroll
    for (int mi = 0; mi < 4; mi++)
#pragma unroll
        for (int ni = 0; ni < 8; ni++)
#pragma unroll
            for (int c = 0; c < 4; c++) acc[mi][ni][c] = 0.f;

    // loads: 128 rows x 16 floats (4 float4) per operand per chunk
    const int row_ = tid >> 2;             // 0..31 (+32 per rep)
    const int kv_  = tid & 3;              // float4 index in 16-float row

    auto issue = [&](int c, int s) {
        const int k0 = c * 16;
#pragma unroll
        for (int i = 0; i < 4; i++) {
            const int row = row_ + i * 32;
            const uint32_t off = (s * GTILE + row * ASTRIDE + kv_ * 4) * 4;
            cp_async16(sA + off, A + (size_t)(m0 + row) * EMB + k0 + kv_ * 4);
            cp_async16(sB + off, W + (size_t)(n0 + row) * EMB + k0 + kv_ * 4);
        }
    };

    issue(0, 0);
    CP_COMMIT();

    for (int c = 0; c < 64; c++) {
        const int s = c & 1;
        __syncthreads();               // stage s^1 readers done (iter c-1)
        if (c < 63) issue(c + 1, s ^ 1);
        CP_COMMIT();
        CP_WAIT1();                    // stage s data arrived
        __syncthreads();

        const float* Af = sm + s * GTILE;
        const float* Bf = sm + 2 * GTILE + s * GTILE;
#pragma unroll
        for (int ks = 0; ks < 2; ks++) {
            const int kc = ks * 8;
            uint32_t afr[4][4];
#pragma unroll
            for (int mi = 0; mi < 4; mi++) {
                const int rb_ = wm0 + mi * 16;
                afr[mi][0] = f2tf(Af[(rb_ + g) * ASTRIDE + kc + t]);
                afr[mi][1] = f2tf(Af[(rb_ + g + 8) * ASTRIDE + kc + t]);
                afr[mi][2] = f2tf(Af[(rb_ + g) * ASTRIDE + kc + t + 4]);
                afr[mi][3] = f2tf(Af[(rb_ + g + 8) * ASTRIDE + kc + t + 4]);
            }
            uint32_t bfr[8][2];
#pragma unroll
            for (int ni = 0; ni < 8; ni++) {
                const int nb = wn0 + ni * 8;
                bfr[ni][0] = f2tf(Bf[(nb + g) * ASTRIDE + kc + t]);
                bfr[ni][1] = f2tf(Bf[(nb + g) * ASTRIDE + kc + t + 4]);
            }
#pragma unroll
            for (int mi = 0; mi < 4; mi++)
#pragma unroll
                for (int ni = 0; ni < 8; ni++)
                    mma_tf32(acc[mi][ni], afr[mi], bfr[ni]);
        }
    }

#pragma unroll
    for (int mi = 0; mi < 4; mi++) {
        const int r_lo = m0 + wm0 + mi * 16 + g;
        const int r_hi = r_lo + 8;
#pragma unroll
        for (int ni = 0; ni < 8; ni++) {
            const int n = n0 + wn0 + ni * 8 + 2 * t;
            const float2 b2 = *(const float2*)(bias + n);
            float2 lo = make_float2(acc[mi][ni][0] + b2.x, acc[mi][ni][1] + b2.y);
            float2 hi = make_float2(acc[mi][ni][2] + b2.x, acc[mi][ni][3] + b2.y);
            if (MODE == 0) {
                *(float2*)(C + (size_t)r_lo * EMB + n) = lo;
                *(float2*)(C + (size_t)r_hi * EMB + n) = hi;
            } else {
                const int h = n >> 6, d = n & 63;
                const int b1_ = r_lo >> 11, t1 = r_lo & 2047;
                const int b2_ = r_hi >> 11, t2 = r_hi & 2047;
                *(float2*)(C + (((size_t)(b1_ * NH + h) * CTX + t1) * HD + d)) = lo;
                *(float2*)(C + (((size_t)(b2_ * NH + h) * CTX + t2) * HD + d)) = hi;
            }
        }
    }
}

__global__ __launch_bounds__(128, 2)
void gemm_proj(const float* __restrict__ A, const float* __restrict__ W,
               const float* __restrict__ bias, float* __restrict__ C) {
    extern __shared__ float smg[];
    gemm_core<0>(A, W, bias, C, smg, blockIdx.y * 128, blockIdx.x * 128);
}

__global__ __launch_bounds__(128, 2)
void gemm_qkv(const float* __restrict__ A,
              const float* __restrict__ W0, const float* __restrict__ b0,
              const float* __restrict__ W1, const float* __restrict__ b1,
              const float* __restrict__ W2, const float* __restrict__ b2,
              float* __restrict__ C0, float* __restrict__ C1,
              float* __restrict__ C2) {
    extern __shared__ float smg[];
    const int z = blockIdx.z;
    const float* W = (z == 0) ? W0 : (z == 1) ? W1 : W2;
    const float* b = (z == 0) ? b0 : (z == 1) ? b1 : b2;
    float* C = (z == 0) ? C0 : (z == 1) ? C1 : C2;
    gemm_core<1>(A, W, b, C, smg, blockIdx.y * 128, blockIdx.x * 128);
}

// ---------------------------------------------------------------------------
// Flash attention (causal), mma.sync tf32 — unchanged (known-good).
// ---------------------------------------------------------------------------
#define KSTR 68
#define ATTN_SMEM ((4 * 64 * KSTR + 128 * KSTR) * 4)

__global__ __launch_bounds__(128, 2)
void attn_kernel(const float* __restrict__ q, const float* __restrict__ k,
                 const float* __restrict__ v, float* __restrict__ o) {
    extern __shared__ uint32_t sm_[];
    uint32_t* Ps = sm_ + 4 * 64 * KSTR;
    const uint32_t sbase = smem_u32(sm_);

    const int tid  = threadIdx.x;
    const int wid  = tid >> 5;
    const int lane = tid & 31;
    const int g    = lane >> 2;
    const int t    = lane & 3;
    const int qt   = blockIdx.x;
    const int bh   = blockIdx.y;
    const int q0   = qt * 128 + wid * 32;
    const int qmax = q0 + 31;

    const float* qbase = q + ((size_t)bh * CTX + q0) * HD;
    const float* kbase = k + (size_t)bh * CTX * HD;
    const float* vbase = v + (size_t)bh * CTX * HD;

    uint32_t qa[2][8][4];
#pragma unroll
    for (int mi = 0; mi < 2; mi++)
#pragma unroll
        for (int ks = 0; ks < 8; ks++) {
            const int kc = ks * 8;
            const int r = mi * 16;
            qa[mi][ks][0] = f2tf(0.125f * qbase[(r + g)     * HD + kc + t]);
            qa[mi][ks][1] = f2tf(0.125f * qbase[(r + g + 8) * HD + kc + t]);
            qa[mi][ks][2] = f2tf(0.125f * qbase[(r + g)     * HD + kc + t + 4]);
            qa[mi][ks][3] = f2tf(0.125f * qbase[(r + g + 8) * HD + kc + t + 4]);
        }

    float oacc[2][8][4];
#pragma unroll
    for (int mi = 0; mi < 2; mi++)
#pragma unroll
        for (int ni = 0; ni < 8; ni++)
#pragma unroll
            for (int c = 0; c < 4; c++) oacc[mi][ni][c] = 0.f;
    float m_[2][2] = {{-1e30f, -1e30f}, {-1e30f, -1e30f}};
    float l_[2][2] = {{0.f, 0.f}, {0.f, 0.f}};

    const int ktmax = 2 * qt + 1;

    auto issue = [&](int kt, int buf) {
#pragma unroll
        for (int i = 0; i < 8; i++) {
            const int it = tid + i * 128;
            const int row = it >> 4;
            const int f4 = it & 15;
            const uint32_t off = (row * KSTR + f4 * 4) * 4;
            cp_async16(sbase + buf * (64 * KSTR * 4) + off,
                       kbase + (size_t)(kt * 64 + row) * HD + f4 * 4);
            cp_async16(sbase + (2 + buf) * (64 * KSTR * 4) + off,
                       vbase + (size_t)(kt * 64 + row) * HD + f4 * 4);
        }
    };

    issue(0, 0);
    CP_COMMIT();

    for (int kt = 0; kt <= ktmax; kt++) {
        const int buf = kt & 1;
        if (kt < ktmax) issue(kt + 1, buf ^ 1);
        CP_COMMIT();
        CP_WAIT1();
        __syncthreads();

        if (kt * 64 <= qmax) {
            const uint32_t* Ks = sm_ + buf * 64 * KSTR;
            const uint32_t* Vs = sm_ + (2 + buf) * 64 * KSTR;

            float sacc[2][8][4];
#pragma unroll
            for (int mi = 0; mi < 2; mi++)
#pragma unroll
                for (int ni = 0; ni < 8; ni++)
#pragma unroll
                    for (int c = 0; c < 4; c++) sacc[mi][ni][c] = 0.f;

#pragma unroll
            for (int ks = 0; ks < 8; ks++) {
                const int kc = ks * 8;
#pragma unroll
                for (int ni = 0; ni < 8; ni++) {
                    uint32_t b[2];
                    b[0] = Ks[(ni * 8 + g) * KSTR + kc + t];
                    b[1] = Ks[(ni * 8 + g) * KSTR + kc + t + 4];
                    mma_tf32(sacc[0][ni], qa[0][ks], b);
                    mma_tf32(sacc[1][ni], qa[1][ks], b);
                }
            }

            if (kt * 64 + 63 > q0) {
#pragma unroll
                for (int mi = 0; mi < 2; mi++) {
                    const int r_lo = q0 + mi * 16 + g;
                    const int r_hi = r_lo + 8;
#pragma unroll
                    for (int ni = 0; ni < 8; ni++) {
                        const int c0 = kt * 64 + ni * 8 + 2 * t;
                        if (c0 > r_lo)     sacc[mi][ni][0] = -1e30f;
                        if (c0 + 1 > r_lo) sacc[mi][ni][1] = -1e30f;
                        if (c0 > r_hi)     sacc[mi][ni][2] = -1e30f;
                        if (c0 + 1 > r_hi) sacc[mi][ni][3] = -1e30f;
                    }
                }
            }

#pragma unroll
            for (int mi = 0; mi < 2; mi++) {
                float rmx_lo = -1e30f, rmx_hi = -1e30f;
#pragma unroll
                for (int ni = 0; ni < 8; ni++) {
                    rmx_lo = fmaxf(rmx_lo, fmaxf(sacc[mi][ni][0], sacc[mi][ni][1]));
                    rmx_hi = fmaxf(rmx_hi, fmaxf(sacc[mi][ni][2], sacc[mi][ni][3]));
                }
                rmx_lo = fmaxf(rmx_lo, __shfl_xor_sync(0xffffffffu, rmx_lo, 1));
                rmx_lo = fmaxf(rmx_lo, __shfl_xor_sync(0xffffffffu, rmx_lo, 2));
                rmx_hi = fmaxf(rmx_hi, __shfl_xor_sync(0xffffffffu, rmx_hi, 1));
                rmx_hi = fmaxf(rmx_hi, __shfl_xor_sync(0xffffffffu, rmx_hi, 2));

                const float mn_lo = fmaxf(m_[mi][0], rmx_lo);
                const float mn_hi = fmaxf(m_[mi][1], rmx_hi);
                const float sc_lo = __expf(m_[mi][0] - mn_lo);
                const float sc_hi = __expf(m_[mi][1] - mn_hi);
                m_[mi][0] = mn_lo; m_[mi][1] = mn_hi;

                float rs_lo = 0.f, rs_hi = 0.f;
#pragma unroll
                for (int ni = 0; ni < 8; ni++) {
                    sacc[mi][ni][0] = __expf(sacc[mi][ni][0] - mn_lo);
                    sacc[mi][ni][1] = __expf(sacc[mi][ni][1] - mn_lo);
                    sacc[mi][ni][2] = __expf(sacc[mi][ni][2] - mn_hi);
                    sacc[mi][ni][3] = __expf(sacc[mi][ni][3] - mn_hi);
                    rs_lo += sacc[mi][ni][0] + sacc[mi][ni][1];
                    rs_hi += sacc[mi][ni][2] + sacc[mi][ni][3];
                }
                rs_lo += __shfl_xor_sync(0xffffffffu, rs_lo, 1);
                rs_lo += __shfl_xor_sync(0xffffffffu, rs_lo, 2);
                rs_hi += __shfl_xor_sync(0xffffffffu, rs_hi, 1);
                rs_hi += __shfl_xor_sync(0xffffffffu, rs_hi, 2);
                l_[mi][0] = l_[mi][0] * sc_lo + rs_lo;
                l_[mi][1] = l_[mi][1] * sc_hi + rs_hi;
#pragma unroll
                for (int ni = 0; ni < 8; ni++) {
                    oacc[mi][ni][0] *= sc_lo; oacc[mi][ni][1] *= sc_lo;
                    oacc[mi][ni][2] *= sc_hi; oacc[mi][ni][3] *= sc_hi;
                }

                const int pr_lo = wid * 32 + mi * 16 + g;
                const int pr_hi = pr_lo + 8;
#pragma unroll
                for (int ni = 0; ni < 8; ni++) {
                    *(uint2*)(Ps + pr_lo * KSTR + ni * 8 + 2 * t) =
                        make_uint2(f2tf(sacc[mi][ni][0]), f2tf(sacc[mi][ni][1]));
                    *(uint2*)(Ps + pr_hi * KSTR + ni * 8 + 2 * t) =
                        make_uint2(f2tf(sacc[mi][ni][2]), f2tf(sacc[mi][ni][3]));
                }
            }
            __syncwarp();

#pragma unroll
            for (int ks = 0; ks < 8; ks++) {
                const int kc = ks * 8;
                uint32_t pa0[4], pa1[4];
                const int pb = wid * 32;
                pa0[0] = Ps[(pb + g) * KSTR + kc + t];
                pa0[1] = Ps[(pb + g + 8) * KSTR + kc + t];
                pa0[2] = Ps[(pb + g) * KSTR + kc + t + 4];
                pa0[3] = Ps[(pb + g + 8) * KSTR + kc + t + 4];
                pa1[0] = Ps[(pb + 16 + g) * KSTR + kc + t];
                pa1[1] = Ps[(pb + 16 + g + 8) * KSTR + kc + t];
                pa1[2] = Ps[(pb + 16 + g) * KSTR + kc + t + 4];
                pa1[3] = Ps[(pb + 16 + g + 8) * KSTR + kc + t + 4];
#pragma unroll
                for (int ni = 0; ni < 8; ni++) {
                    uint32_t b[2];
                    b[0] = Vs[(kc + t) * KSTR + ni * 8 + g];
                    b[1] = Vs[(kc + t + 4) * KSTR + ni * 8 + g];
                    mma_tf32(oacc[0][ni], pa0, b);
                    mma_tf32(oacc[1][ni], pa1, b);
                }
            }
        }
        __syncthreads();
    }

    const int b_ = bh >> 4;
    const int h  = bh & 15;
#pragma unroll
    for (int mi = 0; mi < 2; mi++) {
        const float inv_lo = 1.f / l_[mi][0];
        const float inv_hi = 1.f / l_[mi][1];
        const int t_lo = q0 + mi * 16 + g;
        const int t_hi = t_lo + 8;
#pragma unroll
        for (int ni = 0; ni < 8; ni++) {
            const int col = h * HD + ni * 8 + 2 * t;
            *(float2*)(o + ((size_t)(b_ * CTX + t_lo)) * EMB + col) =
                make_float2(oacc[mi][ni][0] * inv_lo, oacc[mi][ni][1] * inv_lo);
            *(float2*)(o + ((size_t)(b_ * CTX + t_hi)) * EMB + col) =
                make_float2(oacc[mi][ni][2] * inv_hi, oacc[mi][ni][3] * inv_hi);
        }
    }
}

// ---------------------------------------------------------------------------
extern "C" void kernel_launch(void* const* d_in, const int* in_sizes, int n_in,
                              void* d_out, int out_size) {
    const float* x  = (const float*)d_in[0];
    const float* Wq = (const float*)d_in[1];
    const float* bq = (const float*)d_in[2];
    const float* Wk = (const float*)d_in[3];
    const float* bk = (const float*)d_in[4];
    const float* Wv = (const float*)d_in[5];
    const float* bv = (const float*)d_in[6];
    const float* Wp = (const float*)d_in[7];
    const float* bp = (const float*)d_in[8];

    float *q, *k, *v, *a;
    cudaGetSymbolAddress((void**)&q, g_q);
    cudaGetSymbolAddress((void**)&k, g_k);
    cudaGetSymbolAddress((void**)&v, g_v);
    cudaGetSymbolAddress((void**)&a, g_a);

    cudaFuncSetAttribute(gemm_qkv,
                         cudaFuncAttributeMaxDynamicSharedMemorySize, GEMM_SMEM);
    cudaFuncSetAttribute(gemm_proj,
                         cudaFuncAttributeMaxDynamicSharedMemorySize, GEMM_SMEM);
    cudaFuncSetAttribute(attn_kernel,
                         cudaFuncAttributeMaxDynamicSharedMemorySize, ATTN_SMEM);

    gemm_qkv<<<dim3(EMB / 128, BT / 128, 3), 128, GEMM_SMEM>>>(
        x, Wq, bq, Wk, bk, Wv, bv, q, k, v);

    attn_kernel<<<dim3(CTX / 128, 4 * NH), 128, ATTN_SMEM>>>(q, k, v, a);

    gemm_proj<<<dim3(EMB / 128, BT / 128), 128, GEMM_SMEM>>>(a, Wp, bp, (float*)d_out);
}

// round 15
// speedup vs baseline: 1.1317x; 1.1317x over previous
#include <cuda_runtime.h>
#include <cstdint>

#define CTX  2048
#define EMB  1024
#define NH   16
#define HD   64
#define BT   8192   // B*T

// Scratch (allocation-free rule: __device__ globals)
__device__ float g_q[BT * EMB];
__device__ float g_k[BT * EMB];
__device__ float g_v[BT * EMB];
__device__ float g_a[BT * EMB];
__device__ float g_xr[BT * EMB];          // pre-rounded x
__device__ float g_wr[4][EMB * EMB];      // pre-rounded Wq,Wk,Wv,Wp

// ======================= helpers ===========================================
__device__ __forceinline__ uint32_t f2tf(float f) {
    uint32_t u;
    asm("cvt.rna.tf32.f32 %0, %1;" : "=r"(u) : "f"(f));
    return u;
}
// D(16x8,f32) += A(16x8,tf32,row) * B(8x8,tf32,col)
__device__ __forceinline__ void mma_tf32(float* d, const uint32_t* a,
                                         const uint32_t* b) {
    asm volatile(
        "mma.sync.aligned.m16n8k8.row.col.f32.tf32.tf32.f32 "
        "{%0,%1,%2,%3}, {%4,%5,%6,%7}, {%8,%9}, {%0,%1,%2,%3};"
        : "+f"(d[0]), "+f"(d[1]), "+f"(d[2]), "+f"(d[3])
        : "r"(a[0]), "r"(a[1]), "r"(a[2]), "r"(a[3]), "r"(b[0]), "r"(b[1]));
}
__device__ __forceinline__ uint32_t smem_u32(const void* p) {
    uint32_t a;
    asm("{ .reg .u64 t; cvta.to.shared.u64 t, %1; cvt.u32.u64 %0, t; }"
        : "=r"(a) : "l"(p));
    return a;
}
__device__ __forceinline__ void cp_async16(uint32_t dst, const void* src) {
    asm volatile("cp.async.cg.shared.global [%0], [%1], 16;"
                 :: "r"(dst), "l"(src));
}
#define CP_COMMIT() asm volatile("cp.async.commit_group;" ::: "memory")
#define CP_WAIT0()  asm volatile("cp.async.wait_group 0;" ::: "memory")
#define CP_WAIT1()  asm volatile("cp.async.wait_group 1;" ::: "memory")

// ---------------------------------------------------------------------------
// Pre-round: dst[i] = tf32_rna(src[i])  (streaming, memory-bound)
// ---------------------------------------------------------------------------
__global__ __launch_bounds__(256)
void round_tf32(const float* __restrict__ src, float* __restrict__ dst) {
    const int i = (blockIdx.x * 256 + threadIdx.x) * 4;
    float4 v = *(const float4*)(src + i);
    uint4 u = make_uint4(f2tf(v.x), f2tf(v.y), f2tf(v.z), f2tf(v.w));
    *(uint4*)(dst + i) = u;
}

// ---------------------------------------------------------------------------
// GEMM core: C[m,n] = sum_k A[m,k] * W[n,k] + bias[n]
// CTA 128x128, 128 thr / 4 warps, warp tile 64x64, chunk 32.
// 3-stage cp.async ring, ONE barrier + ONE wait per chunk.
// Operands are PRE-ROUNDED to tf32 (rna) -> raw bit loads in mainloop.
// MODE 0: row-major out.  MODE 1: scatter to (B,H,T,D).
// ---------------------------------------------------------------------------
#define ASTRIDE 36
#define GTILE (128 * ASTRIDE)               // 4608 floats per operand stage
#define GEMM_SMEM (6 * GTILE * 4)           // 3 stages x (A+B) = 110592 B

template <int MODE>
__device__ __forceinline__
void gemm_core(const float* __restrict__ A, const float* __restrict__ W,
               const float* __restrict__ bias, float* __restrict__ C,
               float* sm, int m0, int n0) {
    const uint32_t sA = smem_u32(sm);
    const uint32_t sB = sA + 3 * GTILE * 4;

    const int tid  = threadIdx.x;
    const int wid  = tid >> 5;
    const int lane = tid & 31;
    const int g    = lane >> 2;
    const int t    = lane & 3;
    const int wm0  = (wid >> 1) * 64;
    const int wn0  = (wid & 1) * 64;

    float acc[4][8][4];
#pragma unroll
    for (int mi = 0; mi < 4; mi++)
#pragma unroll
        for (int ni = 0; ni < 8; ni++)
#pragma unroll
            for (int c = 0; c < 4; c++) acc[mi][ni][c] = 0.f;

    const int row_ = tid >> 3;              // 0..15 (+16 per rep)
    const int kv_  = tid & 7;

    auto issue = [&](int c, int s) {
        const int k0 = c * 32;
#pragma unroll
        for (int i = 0; i < 8; i++) {
            const int row = row_ + i * 16;
            const uint32_t off = (s * GTILE + row * ASTRIDE + kv_ * 4) * 4;
            cp_async16(sA + off, A + (size_t)(m0 + row) * EMB + k0 + kv_ * 4);
            cp_async16(sB + off, W + (size_t)(n0 + row) * EMB + k0 + kv_ * 4);
        }
    };

    issue(0, 0); CP_COMMIT();
    issue(1, 1); CP_COMMIT();

    int s = 0;               // stage of chunk c (mod-3 ring, kept in register)
    int s2 = 2;              // stage of chunk c+2
#pragma unroll 1
    for (int c = 0; c < 32; c++) {
        if (c == 31) { CP_WAIT0(); } else { CP_WAIT1(); }
        __syncthreads();
        if (c < 30) { issue(c + 2, s2); CP_COMMIT(); }

        const uint32_t* Af = (const uint32_t*)sm + s * GTILE;
        const uint32_t* Bf = (const uint32_t*)sm + 3 * GTILE + s * GTILE;
#pragma unroll
        for (int ks = 0; ks < 4; ks++) {
            const int kc = ks * 8;
            uint32_t afr[4][4];
#pragma unroll
            for (int mi = 0; mi < 4; mi++) {
                const int rb_ = wm0 + mi * 16;
                afr[mi][0] = Af[(rb_ + g) * ASTRIDE + kc + t];
                afr[mi][1] = Af[(rb_ + g + 8) * ASTRIDE + kc + t];
                afr[mi][2] = Af[(rb_ + g) * ASTRIDE + kc + t + 4];
                afr[mi][3] = Af[(rb_ + g + 8) * ASTRIDE + kc + t + 4];
            }
            uint32_t bfr[8][2];
#pragma unroll
            for (int ni = 0; ni < 8; ni++) {
                const int nb = wn0 + ni * 8;
                bfr[ni][0] = Bf[(nb + g) * ASTRIDE + kc + t];
                bfr[ni][1] = Bf[(nb + g) * ASTRIDE + kc + t + 4];
            }
#pragma unroll
            for (int mi = 0; mi < 4; mi++)
#pragma unroll
                for (int ni = 0; ni < 8; ni++)
                    mma_tf32(acc[mi][ni], afr[mi], bfr[ni]);
        }
        s = (s == 2) ? 0 : s + 1;
        s2 = (s2 == 2) ? 0 : s2 + 1;
    }

#pragma unroll
    for (int mi = 0; mi < 4; mi++) {
        const int r_lo = m0 + wm0 + mi * 16 + g;
        const int r_hi = r_lo + 8;
#pragma unroll
        for (int ni = 0; ni < 8; ni++) {
            const int n = n0 + wn0 + ni * 8 + 2 * t;
            const float2 b2 = *(const float2*)(bias + n);
            float2 lo = make_float2(acc[mi][ni][0] + b2.x, acc[mi][ni][1] + b2.y);
            float2 hi = make_float2(acc[mi][ni][2] + b2.x, acc[mi][ni][3] + b2.y);
            if (MODE == 0) {
                *(float2*)(C + (size_t)r_lo * EMB + n) = lo;
                *(float2*)(C + (size_t)r_hi * EMB + n) = hi;
            } else {
                const int h = n >> 6, d = n & 63;
                const int b1_ = r_lo >> 11, t1 = r_lo & 2047;
                const int b2_ = r_hi >> 11, t2 = r_hi & 2047;
                *(float2*)(C + (((size_t)(b1_ * NH + h) * CTX + t1) * HD + d)) = lo;
                *(float2*)(C + (((size_t)(b2_ * NH + h) * CTX + t2) * HD + d)) = hi;
            }
        }
    }
}

__global__ __launch_bounds__(128, 1)
void gemm_proj(const float* __restrict__ A, const float* __restrict__ W,
               const float* __restrict__ bias, float* __restrict__ C) {
    extern __shared__ float smg[];
    gemm_core<0>(A, W, bias, C, smg, blockIdx.y * 128, blockIdx.x * 128);
}

__global__ __launch_bounds__(128, 1)
void gemm_qkv(const float* __restrict__ A,
              const float* __restrict__ Wr,   // g_wr base (4 matrices)
              const float* __restrict__ b0, const float* __restrict__ b1,
              const float* __restrict__ b2,
              float* __restrict__ C0, float* __restrict__ C1,
              float* __restrict__ C2) {
    extern __shared__ float smg[];
    const int z = blockIdx.z;
    const float* W = Wr + (size_t)z * EMB * EMB;
    const float* b = (z == 0) ? b0 : (z == 1) ? b1 : b2;
    float* C = (z == 0) ? C0 : (z == 1) ? C1 : C2;
    gemm_core<1>(A, W, b, C, smg, blockIdx.y * 128, blockIdx.x * 128);
}

// ---------------------------------------------------------------------------
// Flash attention (causal), mma.sync tf32 — known-good structure; epilogue
// stores tf32-rounded output so gemm_proj can consume raw bits.
// ---------------------------------------------------------------------------
#define KSTR 68
#define ATTN_SMEM ((4 * 64 * KSTR + 128 * KSTR) * 4)

__global__ __launch_bounds__(128, 2)
void attn_kernel(const float* __restrict__ q, const float* __restrict__ k,
                 const float* __restrict__ v, float* __restrict__ o) {
    extern __shared__ uint32_t sm_[];
    uint32_t* Ps = sm_ + 4 * 64 * KSTR;
    const uint32_t sbase = smem_u32(sm_);

    const int tid  = threadIdx.x;
    const int wid  = tid >> 5;
    const int lane = tid & 31;
    const int g    = lane >> 2;
    const int t    = lane & 3;
    const int qt   = blockIdx.x;
    const int bh   = blockIdx.y;
    const int q0   = qt * 128 + wid * 32;
    const int qmax = q0 + 31;

    const float* qbase = q + ((size_t)bh * CTX + q0) * HD;
    const float* kbase = k + (size_t)bh * CTX * HD;
    const float* vbase = v + (size_t)bh * CTX * HD;

    uint32_t qa[2][8][4];
#pragma unroll
    for (int mi = 0; mi < 2; mi++)
#pragma unroll
        for (int ks = 0; ks < 8; ks++) {
            const int kc = ks * 8;
            const int r = mi * 16;
            qa[mi][ks][0] = f2tf(0.125f * qbase[(r + g)     * HD + kc + t]);
            qa[mi][ks][1] = f2tf(0.125f * qbase[(r + g + 8) * HD + kc + t]);
            qa[mi][ks][2] = f2tf(0.125f * qbase[(r + g)     * HD + kc + t + 4]);
            qa[mi][ks][3] = f2tf(0.125f * qbase[(r + g + 8) * HD + kc + t + 4]);
        }

    float oacc[2][8][4];
#pragma unroll
    for (int mi = 0; mi < 2; mi++)
#pragma unroll
        for (int ni = 0; ni < 8; ni++)
#pragma unroll
            for (int c = 0; c < 4; c++) oacc[mi][ni][c] = 0.f;
    float m_[2][2] = {{-1e30f, -1e30f}, {-1e30f, -1e30f}};
    float l_[2][2] = {{0.f, 0.f}, {0.f, 0.f}};

    const int ktmax = 2 * qt + 1;

    auto issue = [&](int kt, int buf) {
#pragma unroll
        for (int i = 0; i < 8; i++) {
            const int it = tid + i * 128;
            const int row = it >> 4;
            const int f4 = it & 15;
            const uint32_t off = (row * KSTR + f4 * 4) * 4;
            cp_async16(sbase + buf * (64 * KSTR * 4) + off,
                       kbase + (size_t)(kt * 64 + row) * HD + f4 * 4);
            cp_async16(sbase + (2 + buf) * (64 * KSTR * 4) + off,
                       vbase + (size_t)(kt * 64 + row) * HD + f4 * 4);
        }
    };

    issue(0, 0);
    CP_COMMIT();

    for (int kt = 0; kt <= ktmax; kt++) {
        const int buf = kt & 1;
        if (kt < ktmax) issue(kt + 1, buf ^ 1);
        CP_COMMIT();
        CP_WAIT1();
        __syncthreads();

        if (kt * 64 <= qmax) {
            const uint32_t* Ks = sm_ + buf * 64 * KSTR;
            const uint32_t* Vs = sm_ + (2 + buf) * 64 * KSTR;

            float sacc[2][8][4];
#pragma unroll
            for (int mi = 0; mi < 2; mi++)
#pragma unroll
                for (int ni = 0; ni < 8; ni++)
#pragma unroll
                    for (int c = 0; c < 4; c++) sacc[mi][ni][c] = 0.f;

#pragma unroll
            for (int ks = 0; ks < 8; ks++) {
                const int kc = ks * 8;
#pragma unroll
                for (int ni = 0; ni < 8; ni++) {
                    uint32_t b[2];
                    b[0] = Ks[(ni * 8 + g) * KSTR + kc + t];
                    b[1] = Ks[(ni * 8 + g) * KSTR + kc + t + 4];
                    mma_tf32(sacc[0][ni], qa[0][ks], b);
                    mma_tf32(sacc[1][ni], qa[1][ks], b);
                }
            }

            if (kt * 64 + 63 > q0) {
#pragma unroll
                for (int mi = 0; mi < 2; mi++) {
                    const int r_lo = q0 + mi * 16 + g;
                    const int r_hi = r_lo + 8;
#pragma unroll
                    for (int ni = 0; ni < 8; ni++) {
                        const int c0 = kt * 64 + ni * 8 + 2 * t;
                        if (c0 > r_lo)     sacc[mi][ni][0] = -1e30f;
                        if (c0 + 1 > r_lo) sacc[mi][ni][1] = -1e30f;
                        if (c0 > r_hi)     sacc[mi][ni][2] = -1e30f;
                        if (c0 + 1 > r_hi) sacc[mi][ni][3] = -1e30f;
                    }
                }
            }

#pragma unroll
            for (int mi = 0; mi < 2; mi++) {
                float rmx_lo = -1e30f, rmx_hi = -1e30f;
#pragma unroll
                for (int ni = 0; ni < 8; ni++) {
                    rmx_lo = fmaxf(rmx_lo, fmaxf(sacc[mi][ni][0], sacc[mi][ni][1]));
                    rmx_hi = fmaxf(rmx_hi, fmaxf(sacc[mi][ni][2], sacc[mi][ni][3]));
                }
                rmx_lo = fmaxf(rmx_lo, __shfl_xor_sync(0xffffffffu, rmx_lo, 1));
                rmx_lo = fmaxf(rmx_lo, __shfl_xor_sync(0xffffffffu, rmx_lo, 2));
                rmx_hi = fmaxf(rmx_hi, __shfl_xor_sync(0xffffffffu, rmx_hi, 1));
                rmx_hi = fmaxf(rmx_hi, __shfl_xor_sync(0xffffffffu, rmx_hi, 2));

                const float mn_lo = fmaxf(m_[mi][0], rmx_lo);
                const float mn_hi = fmaxf(m_[mi][1], rmx_hi);
                const float sc_lo = __expf(m_[mi][0] - mn_lo);
                const float sc_hi = __expf(m_[mi][1] - mn_hi);
                m_[mi][0] = mn_lo; m_[mi][1] = mn_hi;

                float rs_lo = 0.f, rs_hi = 0.f;
#pragma unroll
                for (int ni = 0; ni < 8; ni++) {
                    sacc[mi][ni][0] = __expf(sacc[mi][ni][0] - mn_lo);
                    sacc[mi][ni][1] = __expf(sacc[mi][ni][1] - mn_lo);
                    sacc[mi][ni][2] = __expf(sacc[mi][ni][2] - mn_hi);
                    sacc[mi][ni][3] = __expf(sacc[mi][ni][3] - mn_hi);
                    rs_lo += sacc[mi][ni][0] + sacc[mi][ni][1];
                    rs_hi += sacc[mi][ni][2] + sacc[mi][ni][3];
                }
                rs_lo += __shfl_xor_sync(0xffffffffu, rs_lo, 1);
                rs_lo += __shfl_xor_sync(0xffffffffu, rs_lo, 2);
                rs_hi += __shfl_xor_sync(0xffffffffu, rs_hi, 1);
                rs_hi += __shfl_xor_sync(0xffffffffu, rs_hi, 2);
                l_[mi][0] = l_[mi][0] * sc_lo + rs_lo;
                l_[mi][1] = l_[mi][1] * sc_hi + rs_hi;
#pragma unroll
                for (int ni = 0; ni < 8; ni++) {
                    oacc[mi][ni][0] *= sc_lo; oacc[mi][ni][1] *= sc_lo;
                    oacc[mi][ni][2] *= sc_hi; oacc[mi][ni][3] *= sc_hi;
                }

                const int pr_lo = wid * 32 + mi * 16 + g;
                const int pr_hi = pr_lo + 8;
#pragma unroll
                for (int ni = 0; ni < 8; ni++) {
                    *(uint2*)(Ps + pr_lo * KSTR + ni * 8 + 2 * t) =
                        make_uint2(f2tf(sacc[mi][ni][0]), f2tf(sacc[mi][ni][1]));
                    *(uint2*)(Ps + pr_hi * KSTR + ni * 8 + 2 * t) =
                        make_uint2(f2tf(sacc[mi][ni][2]), f2tf(sacc[mi][ni][3]));
                }
            }
            __syncwarp();

#pragma unroll
            for (int ks = 0; ks < 8; ks++) {
                const int kc = ks * 8;
                uint32_t pa0[4], pa1[4];
                const int pb = wid * 32;
                pa0[0] = Ps[(pb + g) * KSTR + kc + t];
                pa0[1] = Ps[(pb + g + 8) * KSTR + kc + t];
                pa0[2] = Ps[(pb + g) * KSTR + kc + t + 4];
                pa0[3] = Ps[(pb + g + 8) * KSTR + kc + t + 4];
                pa1[0] = Ps[(pb + 16 + g) * KSTR + kc + t];
                pa1[1] = Ps[(pb + 16 + g + 8) * KSTR + kc + t];
                pa1[2] = Ps[(pb + 16 + g) * KSTR + kc + t + 4];
                pa1[3] = Ps[(pb + 16 + g + 8) * KSTR + kc + t + 4];
#pragma unroll
                for (int ni = 0; ni < 8; ni++) {
                    uint32_t b[2];
                    b[0] = Vs[(kc + t) * KSTR + ni * 8 + g];
                    b[1] = Vs[(kc + t + 4) * KSTR + ni * 8 + g];
                    mma_tf32(oacc[0][ni], pa0, b);
                    mma_tf32(oacc[1][ni], pa1, b);
                }
            }
        }
        __syncthreads();
    }

    // normalize + write (B,T,N), pre-rounded to tf32 for gemm_proj
    const int b_ = bh >> 4;
    const int h  = bh & 15;
#pragma unroll
    for (int mi = 0; mi < 2; mi++) {
        const float inv_lo = 1.f / l_[mi][0];
        const float inv_hi = 1.f / l_[mi][1];
        const int t_lo = q0 + mi * 16 + g;
        const int t_hi = t_lo + 8;
#pragma unroll
        for (int ni = 0; ni < 8; ni++) {
            const int col = h * HD + ni * 8 + 2 * t;
            *(uint2*)(o + ((size_t)(b_ * CTX + t_lo)) * EMB + col) =
                make_uint2(f2tf(oacc[mi][ni][0] * inv_lo), f2tf(oacc[mi][ni][1] * inv_lo));
            *(uint2*)(o + ((size_t)(b_ * CTX + t_hi)) * EMB + col) =
                make_uint2(f2tf(oacc[mi][ni][2] * inv_hi), f2tf(oacc[mi][ni][3] * inv_hi));
        }
    }
}

// ---------------------------------------------------------------------------
extern "C" void kernel_launch(void* const* d_in, const int* in_sizes, int n_in,
                              void* d_out, int out_size) {
    const float* x  = (const float*)d_in[0];
    const float* Wq = (const float*)d_in[1];
    const float* bq = (const float*)d_in[2];
    const float* Wk = (const float*)d_in[3];
    const float* bk = (const float*)d_in[4];
    const float* Wv = (const float*)d_in[5];
    const float* bv = (const float*)d_in[6];
    const float* Wp = (const float*)d_in[7];
    const float* bp = (const float*)d_in[8];

    float *q, *k, *v, *a, *xr, *wr;
    cudaGetSymbolAddress((void**)&q, g_q);
    cudaGetSymbolAddress((void**)&k, g_k);
    cudaGetSymbolAddress((void**)&v, g_v);
    cudaGetSymbolAddress((void**)&a, g_a);
    cudaGetSymbolAddress((void**)&xr, g_xr);
    cudaGetSymbolAddress((void**)&wr, g_wr);

    cudaFuncSetAttribute(gemm_qkv,
                         cudaFuncAttributeMaxDynamicSharedMemorySize, GEMM_SMEM);
    cudaFuncSetAttribute(gemm_proj,
                         cudaFuncAttributeMaxDynamicSharedMemorySize, GEMM_SMEM);
    cudaFuncSetAttribute(attn_kernel,
                         cudaFuncAttributeMaxDynamicSharedMemorySize, ATTN_SMEM);

    // pre-round operands to tf32 (rna)
    round_tf32<<<BT * EMB / 1024, 256>>>(x, xr);
    round_tf32<<<EMB * EMB / 1024, 256>>>(Wq, wr + 0 * (size_t)EMB * EMB);
    round_tf32<<<EMB * EMB / 1024, 256>>>(Wk, wr + 1 * (size_t)EMB * EMB);
    round_tf32<<<EMB * EMB / 1024, 256>>>(Wv, wr + 2 * (size_t)EMB * EMB);
    round_tf32<<<EMB * EMB / 1024, 256>>>(Wp, wr + 3 * (size_t)EMB * EMB);

    gemm_qkv<<<dim3(EMB / 128, BT / 128, 3), 128, GEMM_SMEM>>>(
        xr, wr, bq, bk, bv, q, k, v);

    attn_kernel<<<dim3(CTX / 128, 4 * NH), 128, ATTN_SMEM>>>(q, k, v, a);

    gemm_proj<<<dim3(EMB / 128, BT / 128), 128, GEMM_SMEM>>>(
        a, wr + 3 * (size_t)EMB * EMB, bp, (float*)d_out);
}

// round 16
// speedup vs baseline: 1.1480x; 1.0144x over previous
#include <cuda_runtime.h>
#include <cstdint>

#define CTX  2048
#define EMB  1024
#define NH   16
#define HD   64
#define BT   8192   // B*T

// Scratch (allocation-free rule: __device__ globals)
__device__ float g_q[BT * EMB];
__device__ float g_k[BT * EMB];
__device__ float g_v[BT * EMB];
__device__ float g_a[BT * EMB];
__device__ float g_xr[BT * EMB];          // pre-rounded x
__device__ float g_wr[4][EMB * EMB];      // pre-rounded Wq,Wk,Wv,Wp

// ======================= helpers ===========================================
__device__ __forceinline__ uint32_t f2tf(float f) {
    uint32_t u;
    asm("cvt.rna.tf32.f32 %0, %1;" : "=r"(u) : "f"(f));
    return u;
}
// D(16x8,f32) += A(16x8,tf32,row) * B(8x8,tf32,col)
__device__ __forceinline__ void mma_tf32(float* d, const uint32_t* a,
                                         const uint32_t* b) {
    asm volatile(
        "mma.sync.aligned.m16n8k8.row.col.f32.tf32.tf32.f32 "
        "{%0,%1,%2,%3}, {%4,%5,%6,%7}, {%8,%9}, {%0,%1,%2,%3};"
        : "+f"(d[0]), "+f"(d[1]), "+f"(d[2]), "+f"(d[3])
        : "r"(a[0]), "r"(a[1]), "r"(a[2]), "r"(a[3]), "r"(b[0]), "r"(b[1]));
}
__device__ __forceinline__ uint32_t smem_u32(const void* p) {
    uint32_t a;
    asm("{ .reg .u64 t; cvta.to.shared.u64 t, %1; cvt.u32.u64 %0, t; }"
        : "=r"(a) : "l"(p));
    return a;
}
__device__ __forceinline__ void cp_async16(uint32_t dst, const void* src) {
    asm volatile("cp.async.cg.shared.global [%0], [%1], 16;"
                 :: "r"(dst), "l"(src));
}
#define CP_COMMIT() asm volatile("cp.async.commit_group;" ::: "memory")
#define CP_WAIT1()  asm volatile("cp.async.wait_group 1;" ::: "memory")

// ---------------------------------------------------------------------------
// Pre-round: dst[i] = tf32_rna(src[i])  (streaming, memory-bound)
// ---------------------------------------------------------------------------
__global__ __launch_bounds__(256)
void round_tf32(const float* __restrict__ src, float* __restrict__ dst) {
    const int i = (blockIdx.x * 256 + threadIdx.x) * 4;
    float4 v = *(const float4*)(src + i);
    uint4 u = make_uint4(f2tf(v.x), f2tf(v.y), f2tf(v.z), f2tf(v.w));
    *(uint4*)(dst + i) = u;
}

// ---------------------------------------------------------------------------
// GEMM core: C[m,n] = sum_k A[m,k] * W[n,k] + bias[n]
// CTA 128x128, 128 thr / 4 warps, warp tile 64x64; chunk 32; 2-stage
// cp.async double buffer (R6 structure: 2 CTAs/SM co-resident).
// Operands PRE-ROUNDED to tf32 (rna) -> raw bit loads, zero cvt in loop.
// MODE 0: row-major out.  MODE 1: scatter to (B,H,T,D).
// ---------------------------------------------------------------------------
#define ASTRIDE 36
#define GTILE (128 * ASTRIDE)               // 4608 floats per operand stage
#define GEMM_SMEM (4 * GTILE * 4)           // A[2]+B[2] = 73728 bytes

template <int MODE>
__device__ __forceinline__
void gemm_core(const float* __restrict__ A, const float* __restrict__ W,
               const float* __restrict__ bias, float* __restrict__ C,
               float* sm, int m0, int n0) {
    const uint32_t sA = smem_u32(sm);
    const uint32_t sB = sA + 2 * GTILE * 4;

    const int tid  = threadIdx.x;
    const int wid  = tid >> 5;
    const int lane = tid & 31;
    const int g    = lane >> 2;
    const int t    = lane & 3;
    const int wm0  = (wid >> 1) * 64;
    const int wn0  = (wid & 1) * 64;

    float acc[4][8][4];
#pragma unroll
    for (int mi = 0; mi < 4; mi++)
#pragma unroll
        for (int ni = 0; ni < 8; ni++)
#pragma unroll
            for (int c = 0; c < 4; c++) acc[mi][ni][c] = 0.f;

    const int row_ = tid >> 3;              // 0..15 (+16 per rep)
    const int kv_  = tid & 7;

    auto issue = [&](int c, int s) {
        const int k0 = c * 32;
#pragma unroll
        for (int i = 0; i < 8; i++) {
            const int row = row_ + i * 16;
            const uint32_t off = (s * GTILE + row * ASTRIDE + kv_ * 4) * 4;
            cp_async16(sA + off, A + (size_t)(m0 + row) * EMB + k0 + kv_ * 4);
            cp_async16(sB + off, W + (size_t)(n0 + row) * EMB + k0 + kv_ * 4);
        }
    };

    issue(0, 0);
    CP_COMMIT();

#pragma unroll 1
    for (int c = 0; c < 32; c++) {
        const int s = c & 1;
        __syncthreads();               // stage s^1 readers done (iter c-1)
        if (c < 31) issue(c + 1, s ^ 1);
        CP_COMMIT();
        CP_WAIT1();                    // stage s data arrived
        __syncthreads();

        const uint32_t* Af = (const uint32_t*)sm + s * GTILE;
        const uint32_t* Bf = (const uint32_t*)sm + 2 * GTILE + s * GTILE;
#pragma unroll
        for (int ks = 0; ks < 4; ks++) {
            const int kc = ks * 8;
            uint32_t afr[4][4];
#pragma unroll
            for (int mi = 0; mi < 4; mi++) {
                const int rb_ = wm0 + mi * 16;
                afr[mi][0] = Af[(rb_ + g) * ASTRIDE + kc + t];
                afr[mi][1] = Af[(rb_ + g + 8) * ASTRIDE + kc + t];
                afr[mi][2] = Af[(rb_ + g) * ASTRIDE + kc + t + 4];
                afr[mi][3] = Af[(rb_ + g + 8) * ASTRIDE + kc + t + 4];
            }
            uint32_t bfr[8][2];
#pragma unroll
            for (int ni = 0; ni < 8; ni++) {
                const int nb = wn0 + ni * 8;
                bfr[ni][0] = Bf[(nb + g) * ASTRIDE + kc + t];
                bfr[ni][1] = Bf[(nb + g) * ASTRIDE + kc + t + 4];
            }
#pragma unroll
            for (int mi = 0; mi < 4; mi++)
#pragma unroll
                for (int ni = 0; ni < 8; ni++)
                    mma_tf32(acc[mi][ni], afr[mi], bfr[ni]);
        }
    }

#pragma unroll
    for (int mi = 0; mi < 4; mi++) {
        const int r_lo = m0 + wm0 + mi * 16 + g;
        const int r_hi = r_lo + 8;
#pragma unroll
        for (int ni = 0; ni < 8; ni++) {
            const int n = n0 + wn0 + ni * 8 + 2 * t;
            const float2 b2 = *(const float2*)(bias + n);
            float2 lo = make_float2(acc[mi][ni][0] + b2.x, acc[mi][ni][1] + b2.y);
            float2 hi = make_float2(acc[mi][ni][2] + b2.x, acc[mi][ni][3] + b2.y);
            if (MODE == 0) {
                *(float2*)(C + (size_t)r_lo * EMB + n) = lo;
                *(float2*)(C + (size_t)r_hi * EMB + n) = hi;
            } else {
                const int h = n >> 6, d = n & 63;
                const int b1_ = r_lo >> 11, t1 = r_lo & 2047;
                const int b2_ = r_hi >> 11, t2 = r_hi & 2047;
                *(float2*)(C + (((size_t)(b1_ * NH + h) * CTX + t1) * HD + d)) = lo;
                *(float2*)(C + (((size_t)(b2_ * NH + h) * CTX + t2) * HD + d)) = hi;
            }
        }
    }
}

__global__ __launch_bounds__(128, 2)
void gemm_proj(const float* __restrict__ A, const float* __restrict__ W,
               const float* __restrict__ bias, float* __restrict__ C) {
    extern __shared__ float smg[];
    gemm_core<0>(A, W, bias, C, smg, blockIdx.y * 128, blockIdx.x * 128);
}

__global__ __launch_bounds__(128, 2)
void gemm_qkv(const float* __restrict__ A,
              const float* __restrict__ Wr,   // g_wr base (4 matrices)
              const float* __restrict__ b0, const float* __restrict__ b1,
              const float* __restrict__ b2,
              float* __restrict__ C0, float* __restrict__ C1,
              float* __restrict__ C2) {
    extern __shared__ float smg[];
    const int z = blockIdx.z;
    const float* W = Wr + (size_t)z * EMB * EMB;
    const float* b = (z == 0) ? b0 : (z == 1) ? b1 : b2;
    float* C = (z == 0) ? C0 : (z == 1) ? C1 : C2;
    gemm_core<1>(A, W, b, C, smg, blockIdx.y * 128, blockIdx.x * 128);
}

// ---------------------------------------------------------------------------
// Flash attention (causal), mma.sync tf32.
// Heavy-first schedule: qt reversed vs blockIdx.x (triangular work; big
// CTAs launch first, shrinking the tail makespan).
// Epilogue stores tf32-rounded output so gemm_proj consumes raw bits.
// ---------------------------------------------------------------------------
#define KSTR 68
#define ATTN_SMEM ((4 * 64 * KSTR + 128 * KSTR) * 4)

__global__ __launch_bounds__(128, 2)
void attn_kernel(const float* __restrict__ q, const float* __restrict__ k,
                 const float* __restrict__ v, float* __restrict__ o) {
    extern __shared__ uint32_t sm_[];
    uint32_t* Ps = sm_ + 4 * 64 * KSTR;
    const uint32_t sbase = smem_u32(sm_);

    const int tid  = threadIdx.x;
    const int wid  = tid >> 5;
    const int lane = tid & 31;
    const int g    = lane >> 2;
    const int t    = lane & 3;
    const int qt   = gridDim.x - 1 - blockIdx.x;   // heavy-first
    const int bh   = blockIdx.y;
    const int q0   = qt * 128 + wid * 32;
    const int qmax = q0 + 31;

    const float* qbase = q + ((size_t)bh * CTX + q0) * HD;
    const float* kbase = k + (size_t)bh * CTX * HD;
    const float* vbase = v + (size_t)bh * CTX * HD;

    uint32_t qa[2][8][4];
#pragma unroll
    for (int mi = 0; mi < 2; mi++)
#pragma unroll
        for (int ks = 0; ks < 8; ks++) {
            const int kc = ks * 8;
            const int r = mi * 16;
            qa[mi][ks][0] = f2tf(0.125f * qbase[(r + g)     * HD + kc + t]);
            qa[mi][ks][1] = f2tf(0.125f * qbase[(r + g + 8) * HD + kc + t]);
            qa[mi][ks][2] = f2tf(0.125f * qbase[(r + g)     * HD + kc + t + 4]);
            qa[mi][ks][3] = f2tf(0.125f * qbase[(r + g + 8) * HD + kc + t + 4]);
        }

    float oacc[2][8][4];
#pragma unroll
    for (int mi = 0; mi < 2; mi++)
#pragma unroll
        for (int ni = 0; ni < 8; ni++)
#pragma unroll
            for (int c = 0; c < 4; c++) oacc[mi][ni][c] = 0.f;
    float m_[2][2] = {{-1e30f, -1e30f}, {-1e30f, -1e30f}};
    float l_[2][2] = {{0.f, 0.f}, {0.f, 0.f}};

    const int ktmax = 2 * qt + 1;

    auto issue = [&](int kt, int buf) {
#pragma unroll
        for (int i = 0; i < 8; i++) {
            const int it = tid + i * 128;
            const int row = it >> 4;
            const int f4 = it & 15;
            const uint32_t off = (row * KSTR + f4 * 4) * 4;
            cp_async16(sbase + buf * (64 * KSTR * 4) + off,
                       kbase + (size_t)(kt * 64 + row) * HD + f4 * 4);
            cp_async16(sbase + (2 + buf) * (64 * KSTR * 4) + off,
                       vbase + (size_t)(kt * 64 + row) * HD + f4 * 4);
        }
    };

    issue(0, 0);
    CP_COMMIT();

    for (int kt = 0; kt <= ktmax; kt++) {
        const int buf = kt & 1;
        if (kt < ktmax) issue(kt + 1, buf ^ 1);
        CP_COMMIT();
        CP_WAIT1();
        __syncthreads();

        if (kt * 64 <= qmax) {
            const uint32_t* Ks = sm_ + buf * 64 * KSTR;
            const uint32_t* Vs = sm_ + (2 + buf) * 64 * KSTR;

            float sacc[2][8][4];
#pragma unroll
            for (int mi = 0; mi < 2; mi++)
#pragma unroll
                for (int ni = 0; ni < 8; ni++)
#pragma unroll
                    for (int c = 0; c < 4; c++) sacc[mi][ni][c] = 0.f;

#pragma unroll
            for (int ks = 0; ks < 8; ks++) {
                const int kc = ks * 8;
#pragma unroll
                for (int ni = 0; ni < 8; ni++) {
                    uint32_t b[2];
                    b[0] = Ks[(ni * 8 + g) * KSTR + kc + t];
                    b[1] = Ks[(ni * 8 + g) * KSTR + kc + t + 4];
                    mma_tf32(sacc[0][ni], qa[0][ks], b);
                    mma_tf32(sacc[1][ni], qa[1][ks], b);
                }
            }

            if (kt * 64 + 63 > q0) {
#pragma unroll
                for (int mi = 0; mi < 2; mi++) {
                    const int r_lo = q0 + mi * 16 + g;
                    const int r_hi = r_lo + 8;
#pragma unroll
                    for (int ni = 0; ni < 8; ni++) {
                        const int c0 = kt * 64 + ni * 8 + 2 * t;
                        if (c0 > r_lo)     sacc[mi][ni][0] = -1e30f;
                        if (c0 + 1 > r_lo) sacc[mi][ni][1] = -1e30f;
                        if (c0 > r_hi)     sacc[mi][ni][2] = -1e30f;
                        if (c0 + 1 > r_hi) sacc[mi][ni][3] = -1e30f;
                    }
                }
            }

#pragma unroll
            for (int mi = 0; mi < 2; mi++) {
                float rmx_lo = -1e30f, rmx_hi = -1e30f;
#pragma unroll
                for (int ni = 0; ni < 8; ni++) {
                    rmx_lo = fmaxf(rmx_lo, fmaxf(sacc[mi][ni][0], sacc[mi][ni][1]));
                    rmx_hi = fmaxf(rmx_hi, fmaxf(sacc[mi][ni][2], sacc[mi][ni][3]));
                }
                rmx_lo = fmaxf(rmx_lo, __shfl_xor_sync(0xffffffffu, rmx_lo, 1));
                rmx_lo = fmaxf(rmx_lo, __shfl_xor_sync(0xffffffffu, rmx_lo, 2));
                rmx_hi = fmaxf(rmx_hi, __shfl_xor_sync(0xffffffffu, rmx_hi, 1));
                rmx_hi = fmaxf(rmx_hi, __shfl_xor_sync(0xffffffffu, rmx_hi, 2));

                const float mn_lo = fmaxf(m_[mi][0], rmx_lo);
                const float mn_hi = fmaxf(m_[mi][1], rmx_hi);
                const float sc_lo = __expf(m_[mi][0] - mn_lo);
                const float sc_hi = __expf(m_[mi][1] - mn_hi);
                m_[mi][0] = mn_lo; m_[mi][1] = mn_hi;

                float rs_lo = 0.f, rs_hi = 0.f;
#pragma unroll
                for (int ni = 0; ni < 8; ni++) {
                    sacc[mi][ni][0] = __expf(sacc[mi][ni][0] - mn_lo);
                    sacc[mi][ni][1] = __expf(sacc[mi][ni][1] - mn_lo);
                    sacc[mi][ni][2] = __expf(sacc[mi][ni][2] - mn_hi);
                    sacc[mi][ni][3] = __expf(sacc[mi][ni][3] - mn_hi);
                    rs_lo += sacc[mi][ni][0] + sacc[mi][ni][1];
                    rs_hi += sacc[mi][ni][2] + sacc[mi][ni][3];
                }
                rs_lo += __shfl_xor_sync(0xffffffffu, rs_lo, 1);
                rs_lo += __shfl_xor_sync(0xffffffffu, rs_lo, 2);
                rs_hi += __shfl_xor_sync(0xffffffffu, rs_hi, 1);
                rs_hi += __shfl_xor_sync(0xffffffffu, rs_hi, 2);
                l_[mi][0] = l_[mi][0] * sc_lo + rs_lo;
                l_[mi][1] = l_[mi][1] * sc_hi + rs_hi;
#pragma unroll
                for (int ni = 0; ni < 8; ni++) {
                    oacc[mi][ni][0] *= sc_lo; oacc[mi][ni][1] *= sc_lo;
                    oacc[mi][ni][2] *= sc_hi; oacc[mi][ni][3] *= sc_hi;
                }

                const int pr_lo = wid * 32 + mi * 16 + g;
                const int pr_hi = pr_lo + 8;
#pragma unroll
                for (int ni = 0; ni < 8; ni++) {
                    *(uint2*)(Ps + pr_lo * KSTR + ni * 8 + 2 * t) =
                        make_uint2(f2tf(sacc[mi][ni][0]), f2tf(sacc[mi][ni][1]));
                    *(uint2*)(Ps + pr_hi * KSTR + ni * 8 + 2 * t) =
                        make_uint2(f2tf(sacc[mi][ni][2]), f2tf(sacc[mi][ni][3]));
                }
            }
            __syncwarp();

#pragma unroll
            for (int ks = 0; ks < 8; ks++) {
                const int kc = ks * 8;
                uint32_t pa0[4], pa1[4];
                const int pb = wid * 32;
                pa0[0] = Ps[(pb + g) * KSTR + kc + t];
                pa0[1] = Ps[(pb + g + 8) * KSTR + kc + t];
                pa0[2] = Ps[(pb + g) * KSTR + kc + t + 4];
                pa0[3] = Ps[(pb + g + 8) * KSTR + kc + t + 4];
                pa1[0] = Ps[(pb + 16 + g) * KSTR + kc + t];
                pa1[1] = Ps[(pb + 16 + g + 8) * KSTR + kc + t];
                pa1[2] = Ps[(pb + 16 + g) * KSTR + kc + t + 4];
                pa1[3] = Ps[(pb + 16 + g + 8) * KSTR + kc + t + 4];
#pragma unroll
                for (int ni = 0; ni < 8; ni++) {
                    uint32_t b[2];
                    b[0] = Vs[(kc + t) * KSTR + ni * 8 + g];
                    b[1] = Vs[(kc + t + 4) * KSTR + ni * 8 + g];
                    mma_tf32(oacc[0][ni], pa0, b);
                    mma_tf32(oacc[1][ni], pa1, b);
                }
            }
        }
        __syncthreads();
    }

    // normalize + write (B,T,N), pre-rounded to tf32 for gemm_proj
    const int b_ = bh >> 4;
    const int h  = bh & 15;
#pragma unroll
    for (int mi = 0; mi < 2; mi++) {
        const float inv_lo = 1.f / l_[mi][0];
        const float inv_hi = 1.f / l_[mi][1];
        const int t_lo = q0 + mi * 16 + g;
        const int t_hi = t_lo + 8;
#pragma unroll
        for (int ni = 0; ni < 8; ni++) {
            const int col = h * HD + ni * 8 + 2 * t;
            *(uint2*)(o + ((size_t)(b_ * CTX + t_lo)) * EMB + col) =
                make_uint2(f2tf(oacc[mi][ni][0] * inv_lo), f2tf(oacc[mi][ni][1] * inv_lo));
            *(uint2*)(o + ((size_t)(b_ * CTX + t_hi)) * EMB + col) =
                make_uint2(f2tf(oacc[mi][ni][2] * inv_hi), f2tf(oacc[mi][ni][3] * inv_hi));
        }
    }
}

// ---------------------------------------------------------------------------
extern "C" void kernel_launch(void* const* d_in, const int* in_sizes, int n_in,
                              void* d_out, int out_size) {
    const float* x  = (const float*)d_in[0];
    const float* Wq = (const float*)d_in[1];
    const float* bq = (const float*)d_in[2];
    const float* Wk = (const float*)d_in[3];
    const float* bk = (const float*)d_in[4];
    const float* Wv = (const float*)d_in[5];
    const float* bv = (const float*)d_in[6];
    const float* Wp = (const float*)d_in[7];
    const float* bp = (const float*)d_in[8];

    float *q, *k, *v, *a, *xr, *wr;
    cudaGetSymbolAddress((void**)&q, g_q);
    cudaGetSymbolAddress((void**)&k, g_k);
    cudaGetSymbolAddress((void**)&v, g_v);
    cudaGetSymbolAddress((void**)&a, g_a);
    cudaGetSymbolAddress((void**)&xr, g_xr);
    cudaGetSymbolAddress((void**)&wr, g_wr);

    cudaFuncSetAttribute(gemm_qkv,
                         cudaFuncAttributeMaxDynamicSharedMemorySize, GEMM_SMEM);
    cudaFuncSetAttribute(gemm_proj,
                         cudaFuncAttributeMaxDynamicSharedMemorySize, GEMM_SMEM);
    cudaFuncSetAttribute(attn_kernel,
                         cudaFuncAttributeMaxDynamicSharedMemorySize, ATTN_SMEM);

    // pre-round operands to tf32 (rna)
    round_tf32<<<BT * EMB / 1024, 256>>>(x, xr);
    round_tf32<<<EMB * EMB / 1024, 256>>>(Wq, wr + 0 * (size_t)EMB * EMB);
    round_tf32<<<EMB * EMB / 1024, 256>>>(Wk, wr + 1 * (size_t)EMB * EMB);
    round_tf32<<<EMB * EMB / 1024, 256>>>(Wv, wr + 2 * (size_t)EMB * EMB);
    round_tf32<<<EMB * EMB / 1024, 256>>>(Wp, wr + 3 * (size_t)EMB * EMB);

    gemm_qkv<<<dim3(EMB / 128, BT / 128, 3), 128, GEMM_SMEM>>>(
        xr, wr, bq, bk, bv, q, k, v);

    attn_kernel<<<dim3(CTX / 128, 4 * NH), 128, ATTN_SMEM>>>(q, k, v, a);

    gemm_proj<<<dim3(EMB / 128, BT / 128), 128, GEMM_SMEM>>>(
        a, wr + 3 * (size_t)EMB * EMB, bp, (float*)d_out);
}

// round 17
// speedup vs baseline: 1.1563x; 1.0072x over previous
#include <cuda_runtime.h>
#include <cstdint>

#define CTX  2048
#define EMB  1024
#define NH   16
#define HD   64
#define BT   8192   // B*T

// Scratch (allocation-free rule: __device__ globals)
__device__ float g_q[BT * EMB];
__device__ float g_k[BT * EMB];
__device__ float g_v[BT * EMB];
__device__ float g_a[BT * EMB];
__device__ float g_xr[BT * EMB];          // pre-rounded x
__device__ float g_wr[4][EMB * EMB];      // pre-rounded Wq,Wk,Wv,Wp

// ======================= helpers ===========================================
__device__ __forceinline__ uint32_t f2tf(float f) {
    uint32_t u;
    asm("cvt.rna.tf32.f32 %0, %1;" : "=r"(u) : "f"(f));
    return u;
}
// D(16x8,f32) += A(16x8,tf32,row) * B(8x8,tf32,col)
__device__ __forceinline__ void mma_tf32(float* d, const uint32_t* a,
                                         const uint32_t* b) {
    asm volatile(
        "mma.sync.aligned.m16n8k8.row.col.f32.tf32.tf32.f32 "
        "{%0,%1,%2,%3}, {%4,%5,%6,%7}, {%8,%9}, {%0,%1,%2,%3};"
        : "+f"(d[0]), "+f"(d[1]), "+f"(d[2]), "+f"(d[3])
        : "r"(a[0]), "r"(a[1]), "r"(a[2]), "r"(a[3]), "r"(b[0]), "r"(b[1]));
}
__device__ __forceinline__ uint32_t smem_u32(const void* p) {
    uint32_t a;
    asm("{ .reg .u64 t; cvta.to.shared.u64 t, %1; cvt.u32.u64 %0, t; }"
        : "=r"(a) : "l"(p));
    return a;
}
__device__ __forceinline__ void cp_async16(uint32_t dst, const void* src) {
    asm volatile("cp.async.cg.shared.global [%0], [%1], 16;"
                 :: "r"(dst), "l"(src));
}
#define CP_COMMIT() asm volatile("cp.async.commit_group;" ::: "memory")
#define CP_WAIT1()  asm volatile("cp.async.wait_group 1;" ::: "memory")

// ---------------------------------------------------------------------------
// Pre-round: dst[i] = tf32_rna(src[i])  (streaming, memory-bound)
// ---------------------------------------------------------------------------
__global__ __launch_bounds__(256)
void round_tf32(const float* __restrict__ src, float* __restrict__ dst) {
    const int i = (blockIdx.x * 256 + threadIdx.x) * 4;
    float4 v = *(const float4*)(src + i);
    uint4 u = make_uint4(f2tf(v.x), f2tf(v.y), f2tf(v.z), f2tf(v.w));
    *(uint4*)(dst + i) = u;
}

// Merged W pre-round: 4 matrices in one launch
__global__ __launch_bounds__(256)
void round_w4(const float* __restrict__ w0, const float* __restrict__ w1,
              const float* __restrict__ w2, const float* __restrict__ w3,
              float* __restrict__ dst) {
    const int i = (blockIdx.x * 256 + threadIdx.x) * 4;
    const int z = i >> 20;                 // i / (EMB*EMB)
    const int j = i & (EMB * EMB - 1);
    const float* src = (z == 0) ? w0 : (z == 1) ? w1 : (z == 2) ? w2 : w3;
    float4 v = *(const float4*)(src + j);
    uint4 u = make_uint4(f2tf(v.x), f2tf(v.y), f2tf(v.z), f2tf(v.w));
    *(uint4*)(dst + i) = u;
}

// ---------------------------------------------------------------------------
// GEMM core: C[m,n] = sum_k A[m,k] * W[n,k] + bias[n]
// CTA 128x128, 128 thr / 4 warps, warp tile 64x64; chunk 32; 2-stage
// cp.async double buffer (2 CTAs/SM co-resident).
// Operands PRE-ROUNDED to tf32 (rna) -> raw bit loads, zero cvt in loop.
// MODE 0: row-major out.  MODE 1: scatter to (B,H,T,D).
// ---------------------------------------------------------------------------
#define ASTRIDE 36
#define GTILE (128 * ASTRIDE)               // 4608 floats per operand stage
#define GEMM_SMEM (4 * GTILE * 4)           // A[2]+B[2] = 73728 bytes

template <int MODE>
__device__ __forceinline__
void gemm_core(const float* __restrict__ A, const float* __restrict__ W,
               const float* __restrict__ bias, float* __restrict__ C,
               float* sm, int m0, int n0) {
    const uint32_t sA = smem_u32(sm);
    const uint32_t sB = sA + 2 * GTILE * 4;

    const int tid  = threadIdx.x;
    const int wid  = tid >> 5;
    const int lane = tid & 31;
    const int g    = lane >> 2;
    const int t    = lane & 3;
    const int wm0  = (wid >> 1) * 64;
    const int wn0  = (wid & 1) * 64;

    float acc[4][8][4];
#pragma unroll
    for (int mi = 0; mi < 4; mi++)
#pragma unroll
        for (int ni = 0; ni < 8; ni++)
#pragma unroll
            for (int c = 0; c < 4; c++) acc[mi][ni][c] = 0.f;

    const int row_ = tid >> 3;              // 0..15 (+16 per rep)
    const int kv_  = tid & 7;

    auto issue = [&](int c, int s) {
        const int k0 = c * 32;
#pragma unroll
        for (int i = 0; i < 8; i++) {
            const int row = row_ + i * 16;
            const uint32_t off = (s * GTILE + row * ASTRIDE + kv_ * 4) * 4;
            cp_async16(sA + off, A + (size_t)(m0 + row) * EMB + k0 + kv_ * 4);
            cp_async16(sB + off, W + (size_t)(n0 + row) * EMB + k0 + kv_ * 4);
        }
    };

    issue(0, 0);
    CP_COMMIT();

#pragma unroll 1
    for (int c = 0; c < 32; c++) {
        const int s = c & 1;
        __syncthreads();               // stage s^1 readers done (iter c-1)
        if (c < 31) issue(c + 1, s ^ 1);
        CP_COMMIT();
        CP_WAIT1();                    // stage s data arrived
        __syncthreads();

        const uint32_t* Af = (const uint32_t*)sm + s * GTILE;
        const uint32_t* Bf = (const uint32_t*)sm + 2 * GTILE + s * GTILE;
#pragma unroll
        for (int ks = 0; ks < 4; ks++) {
            const int kc = ks * 8;
            uint32_t afr[4][4];
#pragma unroll
            for (int mi = 0; mi < 4; mi++) {
                const int rb_ = wm0 + mi * 16;
                afr[mi][0] = Af[(rb_ + g) * ASTRIDE + kc + t];
                afr[mi][1] = Af[(rb_ + g + 8) * ASTRIDE + kc + t];
                afr[mi][2] = Af[(rb_ + g) * ASTRIDE + kc + t + 4];
                afr[mi][3] = Af[(rb_ + g + 8) * ASTRIDE + kc + t + 4];
            }
            uint32_t bfr[8][2];
#pragma unroll
            for (int ni = 0; ni < 8; ni++) {
                const int nb = wn0 + ni * 8;
                bfr[ni][0] = Bf[(nb + g) * ASTRIDE + kc + t];
                bfr[ni][1] = Bf[(nb + g) * ASTRIDE + kc + t + 4];
            }
#pragma unroll
            for (int mi = 0; mi < 4; mi++)
#pragma unroll
                for (int ni = 0; ni < 8; ni++)
                    mma_tf32(acc[mi][ni], afr[mi], bfr[ni]);
        }
    }

#pragma unroll
    for (int mi = 0; mi < 4; mi++) {
        const int r_lo = m0 + wm0 + mi * 16 + g;
        const int r_hi = r_lo + 8;
#pragma unroll
        for (int ni = 0; ni < 8; ni++) {
            const int n = n0 + wn0 + ni * 8 + 2 * t;
            const float2 b2 = *(const float2*)(bias + n);
            float2 lo = make_float2(acc[mi][ni][0] + b2.x, acc[mi][ni][1] + b2.y);
            float2 hi = make_float2(acc[mi][ni][2] + b2.x, acc[mi][ni][3] + b2.y);
            if (MODE == 0) {
                *(float2*)(C + (size_t)r_lo * EMB + n) = lo;
                *(float2*)(C + (size_t)r_hi * EMB + n) = hi;
            } else {
                const int h = n >> 6, d = n & 63;
                const int b1_ = r_lo >> 11, t1 = r_lo & 2047;
                const int b2_ = r_hi >> 11, t2 = r_hi & 2047;
                *(float2*)(C + (((size_t)(b1_ * NH + h) * CTX + t1) * HD + d)) = lo;
                *(float2*)(C + (((size_t)(b2_ * NH + h) * CTX + t2) * HD + d)) = hi;
            }
        }
    }
}

__global__ __launch_bounds__(128, 2)
void gemm_proj(const float* __restrict__ A, const float* __restrict__ W,
               const float* __restrict__ bias, float* __restrict__ C) {
    extern __shared__ float smg[];
    gemm_core<0>(A, W, bias, C, smg, blockIdx.y * 128, blockIdx.x * 128);
}

// z-fastest: grid.x = 24 encodes (n-block, z) with z varying fastest so the
// three CTAs sharing one (m,n) A-tile are concurrent -> L2 A-tile sharing.
__global__ __launch_bounds__(128, 2)
void gemm_qkv(const float* __restrict__ A,
              const float* __restrict__ Wr,   // g_wr base (4 matrices)
              const float* __restrict__ b0, const float* __restrict__ b1,
              const float* __restrict__ b2,
              float* __restrict__ C0, float* __restrict__ C1,
              float* __restrict__ C2) {
    extern __shared__ float smg[];
    const int z  = blockIdx.x % 3;
    const int nb = blockIdx.x / 3;
    const float* W = Wr + (size_t)z * EMB * EMB;
    const float* b = (z == 0) ? b0 : (z == 1) ? b1 : b2;
    float* C = (z == 0) ? C0 : (z == 1) ? C1 : C2;
    gemm_core<1>(A, W, b, C, smg, blockIdx.y * 128, nb * 128);
}

// ---------------------------------------------------------------------------
// Flash attention (causal), mma.sync tf32, log2-domain softmax:
// 0.125*log2(e) folded into Q fragments, exp2f everywhere (no FMUL per exp).
// Heavy-first schedule. Epilogue stores tf32-rounded output for gemm_proj.
// ---------------------------------------------------------------------------
#define KSTR 68
#define ATTN_SMEM ((4 * 64 * KSTR + 128 * KSTR) * 4)
#define QSCALE 0.1803368801111204f   // 0.125 * log2(e)

__global__ __launch_bounds__(128, 2)
void attn_kernel(const float* __restrict__ q, const float* __restrict__ k,
                 const float* __restrict__ v, float* __restrict__ o) {
    extern __shared__ uint32_t sm_[];
    uint32_t* Ps = sm_ + 4 * 64 * KSTR;
    const uint32_t sbase = smem_u32(sm_);

    const int tid  = threadIdx.x;
    const int wid  = tid >> 5;
    const int lane = tid & 31;
    const int g    = lane >> 2;
    const int t    = lane & 3;
    const int qt   = gridDim.x - 1 - blockIdx.x;   // heavy-first
    const int bh   = blockIdx.y;
    const int q0   = qt * 128 + wid * 32;
    const int qmax = q0 + 31;

    const float* qbase = q + ((size_t)bh * CTX + q0) * HD;
    const float* kbase = k + (size_t)bh * CTX * HD;
    const float* vbase = v + (size_t)bh * CTX * HD;

    uint32_t qa[2][8][4];
#pragma unroll
    for (int mi = 0; mi < 2; mi++)
#pragma unroll
        for (int ks = 0; ks < 8; ks++) {
            const int kc = ks * 8;
            const int r = mi * 16;
            qa[mi][ks][0] = f2tf(QSCALE * qbase[(r + g)     * HD + kc + t]);
            qa[mi][ks][1] = f2tf(QSCALE * qbase[(r + g + 8) * HD + kc + t]);
            qa[mi][ks][2] = f2tf(QSCALE * qbase[(r + g)     * HD + kc + t + 4]);
            qa[mi][ks][3] = f2tf(QSCALE * qbase[(r + g + 8) * HD + kc + t + 4]);
        }

    float oacc[2][8][4];
#pragma unroll
    for (int mi = 0; mi < 2; mi++)
#pragma unroll
        for (int ni = 0; ni < 8; ni++)
#pragma unroll
            for (int c = 0; c < 4; c++) oacc[mi][ni][c] = 0.f;
    float m_[2][2] = {{-1e30f, -1e30f}, {-1e30f, -1e30f}};
    float l_[2][2] = {{0.f, 0.f}, {0.f, 0.f}};

    const int ktmax = 2 * qt + 1;

    auto issue = [&](int kt, int buf) {
#pragma unroll
        for (int i = 0; i < 8; i++) {
            const int it = tid + i * 128;
            const int row = it >> 4;
            const int f4 = it & 15;
            const uint32_t off = (row * KSTR + f4 * 4) * 4;
            cp_async16(sbase + buf * (64 * KSTR * 4) + off,
                       kbase + (size_t)(kt * 64 + row) * HD + f4 * 4);
            cp_async16(sbase + (2 + buf) * (64 * KSTR * 4) + off,
                       vbase + (size_t)(kt * 64 + row) * HD + f4 * 4);
        }
    };

    issue(0, 0);
    CP_COMMIT();

    for (int kt = 0; kt <= ktmax; kt++) {
        const int buf = kt & 1;
        if (kt < ktmax) issue(kt + 1, buf ^ 1);
        CP_COMMIT();
        CP_WAIT1();
        __syncthreads();

        if (kt * 64 <= qmax) {
            const uint32_t* Ks = sm_ + buf * 64 * KSTR;
            const uint32_t* Vs = sm_ + (2 + buf) * 64 * KSTR;

            float sacc[2][8][4];
#pragma unroll
            for (int mi = 0; mi < 2; mi++)
#pragma unroll
                for (int ni = 0; ni < 8; ni++)
#pragma unroll
                    for (int c = 0; c < 4; c++) sacc[mi][ni][c] = 0.f;

#pragma unroll
            for (int ks = 0; ks < 8; ks++) {
                const int kc = ks * 8;
#pragma unroll
                for (int ni = 0; ni < 8; ni++) {
                    uint32_t b[2];
                    b[0] = Ks[(ni * 8 + g) * KSTR + kc + t];
                    b[1] = Ks[(ni * 8 + g) * KSTR + kc + t + 4];
                    mma_tf32(sacc[0][ni], qa[0][ks], b);
                    mma_tf32(sacc[1][ni], qa[1][ks], b);
                }
            }

            if (kt * 64 + 63 > q0) {
#pragma unroll
                for (int mi = 0; mi < 2; mi++) {
                    const int r_lo = q0 + mi * 16 + g;
                    const int r_hi = r_lo + 8;
#pragma unroll
                    for (int ni = 0; ni < 8; ni++) {
                        const int c0 = kt * 64 + ni * 8 + 2 * t;
                        if (c0 > r_lo)     sacc[mi][ni][0] = -1e30f;
                        if (c0 + 1 > r_lo) sacc[mi][ni][1] = -1e30f;
                        if (c0 > r_hi)     sacc[mi][ni][2] = -1e30f;
                        if (c0 + 1 > r_hi) sacc[mi][ni][3] = -1e30f;
                    }
                }
            }

#pragma unroll
            for (int mi = 0; mi < 2; mi++) {
                float rmx_lo = -1e30f, rmx_hi = -1e30f;
#pragma unroll
                for (int ni = 0; ni < 8; ni++) {
                    rmx_lo = fmaxf(rmx_lo, fmaxf(sacc[mi][ni][0], sacc[mi][ni][1]));
                    rmx_hi = fmaxf(rmx_hi, fmaxf(sacc[mi][ni][2], sacc[mi][ni][3]));
                }
                rmx_lo = fmaxf(rmx_lo, __shfl_xor_sync(0xffffffffu, rmx_lo, 1));
                rmx_lo = fmaxf(rmx_lo, __shfl_xor_sync(0xffffffffu, rmx_lo, 2));
                rmx_hi = fmaxf(rmx_hi, __shfl_xor_sync(0xffffffffu, rmx_hi, 1));
                rmx_hi = fmaxf(rmx_hi, __shfl_xor_sync(0xffffffffu, rmx_hi, 2));

                const float mn_lo = fmaxf(m_[mi][0], rmx_lo);
                const float mn_hi = fmaxf(m_[mi][1], rmx_hi);
                const float sc_lo = exp2f(m_[mi][0] - mn_lo);
                const float sc_hi = exp2f(m_[mi][1] - mn_hi);
                m_[mi][0] = mn_lo; m_[mi][1] = mn_hi;

                float rs_lo = 0.f, rs_hi = 0.f;
#pragma unroll
                for (int ni = 0; ni < 8; ni++) {
                    sacc[mi][ni][0] = exp2f(sacc[mi][ni][0] - mn_lo);
                    sacc[mi][ni][1] = exp2f(sacc[mi][ni][1] - mn_lo);
                    sacc[mi][ni][2] = exp2f(sacc[mi][ni][2] - mn_hi);
                    sacc[mi][ni][3] = exp2f(sacc[mi][ni][3] - mn_hi);
                    rs_lo += sacc[mi][ni][0] + sacc[mi][ni][1];
                    rs_hi += sacc[mi][ni][2] + sacc[mi][ni][3];
                }
                rs_lo += __shfl_xor_sync(0xffffffffu, rs_lo, 1);
                rs_lo += __shfl_xor_sync(0xffffffffu, rs_lo, 2);
                rs_hi += __shfl_xor_sync(0xffffffffu, rs_hi, 1);
                rs_hi += __shfl_xor_sync(0xffffffffu, rs_hi, 2);
                l_[mi][0] = l_[mi][0] * sc_lo + rs_lo;
                l_[mi][1] = l_[mi][1] * sc_hi + rs_hi;
#pragma unroll
                for (int ni = 0; ni < 8; ni++) {
                    oacc[mi][ni][0] *= sc_lo; oacc[mi][ni][1] *= sc_lo;
                    oacc[mi][ni][2] *= sc_hi; oacc[mi][ni][3] *= sc_hi;
                }

                const int pr_lo = wid * 32 + mi * 16 + g;
                const int pr_hi = pr_lo + 8;
#pragma unroll
                for (int ni = 0; ni < 8; ni++) {
                    *(uint2*)(Ps + pr_lo * KSTR + ni * 8 + 2 * t) =
                        make_uint2(f2tf(sacc[mi][ni][0]), f2tf(sacc[mi][ni][1]));
                    *(uint2*)(Ps + pr_hi * KSTR + ni * 8 + 2 * t) =
                        make_uint2(f2tf(sacc[mi][ni][2]), f2tf(sacc[mi][ni][3]));
                }
            }
            __syncwarp();

#pragma unroll
            for (int ks = 0; ks < 8; ks++) {
                const int kc = ks * 8;
                uint32_t pa0[4], pa1[4];
                const int pb = wid * 32;
                pa0[0] = Ps[(pb + g) * KSTR + kc + t];
                pa0[1] = Ps[(pb + g + 8) * KSTR + kc + t];
                pa0[2] = Ps[(pb + g) * KSTR + kc + t + 4];
                pa0[3] = Ps[(pb + g + 8) * KSTR + kc + t + 4];
                pa1[0] = Ps[(pb + 16 + g) * KSTR + kc + t];
                pa1[1] = Ps[(pb + 16 + g + 8) * KSTR + kc + t];
                pa1[2] = Ps[(pb + 16 + g) * KSTR + kc + t + 4];
                pa1[3] = Ps[(pb + 16 + g + 8) * KSTR + kc + t + 4];
#pragma unroll
                for (int ni = 0; ni < 8; ni++) {
                    uint32_t b[2];
                    b[0] = Vs[(kc + t) * KSTR + ni * 8 + g];
                    b[1] = Vs[(kc + t + 4) * KSTR + ni * 8 + g];
                    mma_tf32(oacc[0][ni], pa0, b);
                    mma_tf32(oacc[1][ni], pa1, b);
                }
            }
        }
        __syncthreads();
    }

    // normalize + write (B,T,N), pre-rounded to tf32 for gemm_proj
    const int b_ = bh >> 4;
    const int h  = bh & 15;
#pragma unroll
    for (int mi = 0; mi < 2; mi++) {
        const float inv_lo = 1.f / l_[mi][0];
        const float inv_hi = 1.f / l_[mi][1];
        const int t_lo = q0 + mi * 16 + g;
        const int t_hi = t_lo + 8;
#pragma unroll
        for (int ni = 0; ni < 8; ni++) {
            const int col = h * HD + ni * 8 + 2 * t;
            *(uint2*)(o + ((size_t)(b_ * CTX + t_lo)) * EMB + col) =
                make_uint2(f2tf(oacc[mi][ni][0] * inv_lo), f2tf(oacc[mi][ni][1] * inv_lo));
            *(uint2*)(o + ((size_t)(b_ * CTX + t_hi)) * EMB + col) =
                make_uint2(f2tf(oacc[mi][ni][2] * inv_hi), f2tf(oacc[mi][ni][3] * inv_hi));
        }
    }
}

// ---------------------------------------------------------------------------
extern "C" void kernel_launch(void* const* d_in, const int* in_sizes, int n_in,
                              void* d_out, int out_size) {
    const float* x  = (const float*)d_in[0];
    const float* Wq = (const float*)d_in[1];
    const float* bq = (const float*)d_in[2];
    const float* Wk = (const float*)d_in[3];
    const float* bk = (const float*)d_in[4];
    const float* Wv = (const float*)d_in[5];
    const float* bv = (const float*)d_in[6];
    const float* Wp = (const float*)d_in[7];
    const float* bp = (const float*)d_in[8];

    float *q, *k, *v, *a, *xr, *wr;
    cudaGetSymbolAddress((void**)&q, g_q);
    cudaGetSymbolAddress((void**)&k, g_k);
    cudaGetSymbolAddress((void**)&v, g_v);
    cudaGetSymbolAddress((void**)&a, g_a);
    cudaGetSymbolAddress((void**)&xr, g_xr);
    cudaGetSymbolAddress((void**)&wr, g_wr);

    cudaFuncSetAttribute(gemm_qkv,
                         cudaFuncAttributeMaxDynamicSharedMemorySize, GEMM_SMEM);
    cudaFuncSetAttribute(gemm_proj,
                         cudaFuncAttributeMaxDynamicSharedMemorySize, GEMM_SMEM);
    cudaFuncSetAttribute(attn_kernel,
                         cudaFuncAttributeMaxDynamicSharedMemorySize, ATTN_SMEM);

    // pre-round operands to tf32 (rna)
    round_tf32<<<BT * EMB / 1024, 256>>>(x, xr);
    round_w4<<<4 * EMB * EMB / 1024, 256>>>(Wq, Wk, Wv, Wp, wr);

    gemm_qkv<<<dim3(3 * EMB / 128, BT / 128), 128, GEMM_SMEM>>>(
        xr, wr, bq, bk, bv, q, k, v);

    attn_kernel<<<dim3(CTX / 128, 4 * NH), 128, ATTN_SMEM>>>(q, k, v, a);

    gemm_proj<<<dim3(EMB / 128, BT / 128), 128, GEMM_SMEM>>>(
        a, wr + 3 * (size_t)EMB * EMB, bp, (float*)d_out);
}